// round 9
// baseline (speedup 1.0000x reference)
#include <cuda_runtime.h>

// BaconAdditionReasoner:
//   Wn = rowwise minmax-norm(W);  ap = a @ Wn1;  bp = b @ Wn2
//   A_i = clamp(1-ap_i, 1e-6, 1-1e-6); B_j likewise
//   prod[k] = prod_{i+j=k} max(A_i, B_j)   ( == exp(sum log(1-clip(min))) )
//   y[k] = (1 - prod[k]) / (19 - sum(prod) + 1e-9)
// mask input (d_in[4]) is structurally i+j==k -> hardcoded.
//
// 2 elements/thread; matvecs packed f32x2 sharing weight LDS across both
// elements; epilogue: scalar maxes (no packed f32 min/max exists on sm_103a),
// packed multiplies via parity-split anti-diagonal pairs, streamed over the
// output-pair index to minimize live registers.

#define THREADS 128
#define WARPS (THREADS / 32)
#define ROWS_PER_WARP 64
#define ROWS_PER_BLOCK (THREADS * 2)
#define EPS_LO 1e-6f
#define EPS_HI (1.0f - 1e-6f)

typedef unsigned long long u64;

__device__ __forceinline__ u64 pk2(float x) {
    u64 r; asm("mov.b64 %0, {%1, %1};" : "=l"(r) : "f"(x)); return r;
}
__device__ __forceinline__ u64 mk2(float lo, float hi) {
    u64 r; asm("mov.b64 %0, {%1, %2};" : "=l"(r) : "f"(lo), "f"(hi)); return r;
}
__device__ __forceinline__ void fma2(u64& d, u64 a, u64 b) {
    asm("fma.rn.f32x2 %0, %1, %2, %0;" : "+l"(d) : "l"(a), "l"(b));
}
__device__ __forceinline__ u64 fma2n(u64 a, u64 b, u64 c) {   // d = a*b + c
    u64 r; asm("fma.rn.f32x2 %0, %1, %2, %3;" : "=l"(r) : "l"(a), "l"(b), "l"(c));
    return r;
}
__device__ __forceinline__ u64 mul2(u64 a, u64 b) {
    u64 r; asm("mul.rn.f32x2 %0, %1, %2;" : "=l"(r) : "l"(a), "l"(b)); return r;
}
__device__ __forceinline__ u64 add2(u64 a, u64 b) {
    u64 r; asm("add.rn.f32x2 %0, %1, %2;" : "=l"(r) : "l"(a), "l"(b)); return r;
}
__device__ __forceinline__ float2 upk(u64 v) {
    float2 r; asm("mov.b64 {%0, %1}, %2;" : "=f"(r.x), "=f"(r.y) : "l"(v)); return r;
}
__device__ __forceinline__ float clampP(float x) {
    return fminf(fmaxf(x, EPS_LO), EPS_HI);
}

// Epilogue for one element. A[10], Bv[10] clamped scalars. dst: 19 floats.
// Parity split: pe(x) covers prod pair (2x,2x+1) from even i; po(x) covers
// (2x+1,2x+2) from odd i. Streamed over x = 0..8; prod[18] = last po.hi.
__device__ __forceinline__ void epilogue_pk(const float* A, const float* Bv, float* dst) {
    u64 pr[9];
    float prevHi = 1.0f;
    #pragma unroll
    for (int x = 0; x < 9; ++x) {
        const int elo = (x > 4) ? (x - 4) : 0;
        const int ehi = (x < 4) ? x : 4;
        u64 pe = 0, po = 0;
        #pragma unroll
        for (int e = elo; e <= ehi; ++e) {
            const int t = x - e;                 // i_even=2e, i_odd=2e+1, j pair (2t,2t+1)
            const float Ae = A[2 * e];
            const float Ao = A[2 * e + 1];
            const float B0 = Bv[2 * t];
            const float B1 = Bv[2 * t + 1];
            const u64 me = mk2(fmaxf(Ae, B0), fmaxf(Ae, B1));
            const u64 mo = mk2(fmaxf(Ao, B0), fmaxf(Ao, B1));
            if (e == elo) { pe = me; po = mo; }
            else          { pe = mul2(pe, me); po = mul2(po, mo); }
        }
        const float2 pof = upk(po);
        pr[x] = mul2(pe, mk2(prevHi, pof.x));    // prod[2x] = pe.lo*po(x-1).hi ; prod[2x+1] = pe.hi*po(x).lo
        prevHi = pof.y;
    }
    const float p18 = prevHi;                    // prod[18] = po(8).hi (only term i=9,j=9)

    // sum(prod[0..17]) packed, + p18
    u64 s01 = add2(pr[0], pr[1]);
    u64 s23 = add2(pr[2], pr[3]);
    u64 s45 = add2(pr[4], pr[5]);
    u64 s67 = add2(pr[6], pr[7]);
    s01 = add2(s01, s23);
    s45 = add2(s45, s67);
    s01 = add2(s01, s45);
    s01 = add2(s01, pr[8]);
    const float2 sf = upk(s01);
    const float sp = sf.x + sf.y + p18;

    const float inv = __fdividef(1.0f, (19.0f - sp) + 1e-9f);
    const u64 iv2  = pk2(inv);
    const u64 niv2 = pk2(-inv);

    #pragma unroll
    for (int t = 0; t < 9; ++t) {                // y = inv - prod*inv
        const float2 u = upk(fma2n(pr[t], niv2, iv2));
        dst[2 * t]     = u.x;
        dst[2 * t + 1] = u.y;
    }
    dst[18] = fmaf(-p18, inv, inv);
}

__global__ void __launch_bounds__(THREADS, 7) bacon_kernel(
    const float* __restrict__ p1, const float* __restrict__ p2,
    const float* __restrict__ W1, const float* __restrict__ W2,
    float* __restrict__ out, int B)
{
    // NEGATED normalized weights; row = 5 u64 pairs, padded to 6 (48B) so
    // pairs (c01,c23) and (c45,c67) are 16B-aligned for LDS.128 broadcast.
    __shared__ u64 Wp1[10][6];
    __shared__ u64 Wp2[10][6];
    // Per-warp slice: 1280 floats = p1 tile [0,640) | p2 tile [640,1280).
    // Reused (after syncwarp) as the 64x19=1216-float output tile.
    __shared__ float sbuf[WARPS * 1280];

    const int tid  = threadIdx.x;
    const int wid  = tid >> 5;
    const int lane = tid & 31;

    const size_t warpStart = (size_t)blockIdx.x * ROWS_PER_BLOCK
                           + (size_t)wid * ROWS_PER_WARP;
    const bool wfull = (warpStart + ROWS_PER_WARP) <= (size_t)B;
    float* slice = sbuf + wid * 1280;

    // --- stage 64 rows of p1/p2 FIRST so DRAM latency overlaps the barrier ---
    if (wfull) {
        const float4* s1 = (const float4*)(p1 + warpStart * 10);   // 160 float4
        const float4* s2 = (const float4*)(p2 + warpStart * 10);
        float4* d1 = (float4*)slice;
        float4* d2 = (float4*)(slice + 640);
        #pragma unroll
        for (int it = 0; it < 5; ++it) {
            const int i = lane + it * 32;
            d1[i] = __ldcs(&s1[i]);
            d2[i] = __ldcs(&s2[i]);
        }
    } else {
        const int rows = (warpStart < (size_t)B) ? (int)((size_t)B - warpStart) : 0;
        for (int i = lane; i < 1280; i += 32) slice[i] = 0.0f;
        __syncwarp();
        for (int i = lane; i < rows * 10; i += 32) {
            slice[i]       = p1[warpStart * 10 + i];
            slice[640 + i] = p2[warpStart * 10 + i];
        }
    }

    // --- weight normalization (20 threads; tiny uniform work) ---
    if (tid < 20) {
        const float* W = (tid < 10) ? W1 : W2;
        const int m = tid / 10;
        const int r = tid % 10;
        float row[10];
        #pragma unroll
        for (int c = 0; c < 10; ++c) row[c] = W[r * 10 + c];
        float lo = row[0], hi = row[0];
        #pragma unroll
        for (int c = 1; c < 10; ++c) { lo = fminf(lo, row[c]); hi = fmaxf(hi, row[c]); }
        const float ninv = -1.0f / (hi - lo + 1e-8f);      // negate here
        float* frow = m ? (float*)&Wp2[r][0] : (float*)&Wp1[r][0];
        #pragma unroll
        for (int c = 0; c < 10; ++c) frow[c] = (row[c] - lo) * ninv;
    }
    __syncthreads();   // the ONLY block-wide barrier (weights + own staging)

    const u64 ONE2 = pk2(1.0f);

    float A0[10], A1[10], B0v[10], B1v[10];

    // ---------- Phase A: A = clamp(1 - a @ Wn1), both elements ----------
    {
        float a0[10], a1[10];
        {
            const float2* v0 = (const float2*)(slice + lane * 10);
            const float2* v1 = (const float2*)(slice + (lane + 32) * 10);
            #pragma unroll
            for (int k = 0; k < 5; ++k) {
                float2 w = v0[k]; a0[2 * k] = w.x; a0[2 * k + 1] = w.y;
                float2 u = v1[k]; a1[2 * k] = u.x; a1[2 * k + 1] = u.y;
            }
        }
        u64 c0[5], c1[5];
        #pragma unroll
        for (int t = 0; t < 5; ++t) { c0[t] = ONE2; c1[t] = ONE2; }
        #pragma unroll
        for (int j = 0; j < 10; ++j) {
            const ulonglong2* wr = (const ulonglong2*)&Wp1[j][0];
            const ulonglong2 q0 = wr[0];
            const ulonglong2 q1 = wr[1];
            const u64        q2 = Wp1[j][4];
            const u64 x0 = pk2(a0[j]);
            const u64 x1 = pk2(a1[j]);
            fma2(c0[0], x0, q0.x); fma2(c0[1], x0, q0.y);
            fma2(c0[2], x0, q1.x); fma2(c0[3], x0, q1.y); fma2(c0[4], x0, q2);
            fma2(c1[0], x1, q0.x); fma2(c1[1], x1, q0.y);
            fma2(c1[2], x1, q1.x); fma2(c1[3], x1, q1.y); fma2(c1[4], x1, q2);
        }
        #pragma unroll
        for (int t = 0; t < 5; ++t) {
            float2 u = upk(c0[t]);
            A0[2 * t] = clampP(u.x); A0[2 * t + 1] = clampP(u.y);
            float2 v = upk(c1[t]);
            A1[2 * t] = clampP(v.x); A1[2 * t + 1] = clampP(v.y);
        }
    }

    // ---------- Phase B: B = clamp(1 - b @ Wn2), both elements ----------
    {
        float b0[10], b1[10];
        {
            const float2* v0 = (const float2*)(slice + 640 + lane * 10);
            const float2* v1 = (const float2*)(slice + 640 + (lane + 32) * 10);
            #pragma unroll
            for (int k = 0; k < 5; ++k) {
                float2 w = v0[k]; b0[2 * k] = w.x; b0[2 * k + 1] = w.y;
                float2 u = v1[k]; b1[2 * k] = u.x; b1[2 * k + 1] = u.y;
            }
        }
        u64 c0[5], c1[5];
        #pragma unroll
        for (int t = 0; t < 5; ++t) { c0[t] = ONE2; c1[t] = ONE2; }
        #pragma unroll
        for (int j = 0; j < 10; ++j) {
            const ulonglong2* wr = (const ulonglong2*)&Wp2[j][0];
            const ulonglong2 q0 = wr[0];
            const ulonglong2 q1 = wr[1];
            const u64        q2 = Wp2[j][4];
            const u64 x0 = pk2(b0[j]);
            const u64 x1 = pk2(b1[j]);
            fma2(c0[0], x0, q0.x); fma2(c0[1], x0, q0.y);
            fma2(c0[2], x0, q1.x); fma2(c0[3], x0, q1.y); fma2(c0[4], x0, q2);
            fma2(c1[0], x1, q0.x); fma2(c1[1], x1, q0.y);
            fma2(c1[2], x1, q1.x); fma2(c1[3], x1, q1.y); fma2(c1[4], x1, q2);
        }
        #pragma unroll
        for (int t = 0; t < 5; ++t) {
            float2 u = upk(c0[t]);
            B0v[2 * t] = clampP(u.x); B0v[2 * t + 1] = clampP(u.y);
            float2 v = upk(c1[t]);
            B1v[2 * t] = clampP(v.x); B1v[2 * t + 1] = clampP(v.y);
        }
    }
    __syncwarp();   // all slice reads done; slice becomes output tile

    // ---------- sequential epilogues (caps register pressure) ----------
    {
        float y[19];
        epilogue_pk(A0, B0v, y);
        #pragma unroll
        for (int k = 0; k < 19; ++k) slice[lane * 19 + k] = y[k];
        epilogue_pk(A1, B1v, y);
        #pragma unroll
        for (int k = 0; k < 19; ++k) slice[(lane + 32) * 19 + k] = y[k];
    }
    __syncwarp();

    // ---------- coalesced store of the 64x19 output tile ----------
    if (wfull) {
        float4* dst = (float4*)(out + warpStart * 19);
        const float4* src = (const float4*)slice;
        #pragma unroll
        for (int it = 0; it < 10; ++it) {
            const int i = lane + it * 32;
            if (i < 304) __stcs(&dst[i], src[i]);     // 64*19/4 = 304
        }
    } else {
        const int rows = (warpStart < (size_t)B) ? (int)((size_t)B - warpStart) : 0;
        for (int i = lane; i < rows * 19; i += 32) out[warpStart * 19 + i] = slice[i];
    }
}

extern "C" void kernel_launch(void* const* d_in, const int* in_sizes, int n_in,
                              void* d_out, int out_size) {
    const float* p1 = (const float*)d_in[0];
    const float* p2 = (const float*)d_in[1];
    const float* W1 = (const float*)d_in[2];
    const float* W2 = (const float*)d_in[3];
    // d_in[4] = mask: structurally i+j==k, hardcoded.
    float* out = (float*)d_out;

    const int B = in_sizes[0] / 10;
    const int blocks = (B + ROWS_PER_BLOCK - 1) / ROWS_PER_BLOCK;
    bacon_kernel<<<blocks, THREADS>>>(p1, p2, W1, W2, out, B);
}

// round 11
// speedup vs baseline: 1.0401x; 1.0401x over previous
#include <cuda_runtime.h>

// BaconAdditionReasoner:
//   Wn = rowwise minmax-norm(W);  ap = a @ Wn1;  bp = b @ Wn2
//   A_i = clamp(1-ap_i, 1e-6, 1-1e-6); B_j likewise
//   prod[k] = prod_{i+j=k} max(A_i, B_j)   ( == exp(sum log(1-clip(min))) )
//   y[k] = (1 - prod[k]) / (19 - sum(prod) + 1e-9)
// mask input (d_in[4]) is structurally i+j==k -> hardcoded.
//
// 2 elements/thread; packed f32x2 matvecs sharing weight LDS across both
// elements; scalar-max epilogue (best dependency structure; R8's packed
// variant regressed) writing results straight to shared to cut live regs.

#define THREADS 128
#define WARPS (THREADS / 32)
#define ROWS_PER_WARP 64
#define ROWS_PER_BLOCK (THREADS * 2)
#define EPS_LO 1e-6f
#define EPS_HI (1.0f - 1e-6f)

typedef unsigned long long u64;

__device__ __forceinline__ u64 pk2(float x) {
    u64 r; asm("mov.b64 %0, {%1, %1};" : "=l"(r) : "f"(x)); return r;
}
__device__ __forceinline__ void fma2(u64& d, u64 a, u64 b) {
    asm("fma.rn.f32x2 %0, %1, %2, %0;" : "+l"(d) : "l"(a), "l"(b));
}
__device__ __forceinline__ float2 upk(u64 v) {
    float2 r; asm("mov.b64 {%0, %1}, %2;" : "=f"(r.x), "=f"(r.y) : "l"(v)); return r;
}
__device__ __forceinline__ float clampP(float x) {
    return fminf(fmaxf(x, EPS_LO), EPS_HI);
}

// Scalar epilogue; writes the 19 normalized outputs directly to smem (dst)
// so no 19-register staging buffer stays live.
__device__ __forceinline__ void epilogue(const float* A, const float* Bv,
                                         float* __restrict__ dst) {
    float prod[19];
    #pragma unroll
    for (int k = 0; k < 10; ++k) prod[k] = fmaxf(A[0], Bv[k]);
    #pragma unroll
    for (int i = 1; i < 10; ++i) prod[9 + i] = fmaxf(A[i], Bv[9]);
    #pragma unroll
    for (int i = 1; i < 10; ++i) {
        const float Ai = A[i];
        #pragma unroll
        for (int j = 0; j < 9; ++j) prod[i + j] *= fmaxf(Ai, Bv[j]);
    }
    float sp = 0.0f;
    #pragma unroll
    for (int k = 0; k < 19; ++k) sp += prod[k];
    const float inv = __fdividef(1.0f, (19.0f - sp) + 1e-9f);
    #pragma unroll
    for (int k = 0; k < 19; ++k) dst[k] = fmaf(-prod[k], inv, inv);
}

__global__ void __launch_bounds__(THREADS, 7) bacon_kernel(
    const float* __restrict__ p1, const float* __restrict__ p2,
    const float* __restrict__ W1, const float* __restrict__ W2,
    float* __restrict__ out, int B)
{
    // NEGATED normalized weights; row = 5 u64 pairs, padded to 6 (48B) so
    // pairs (c01,c23) and (c45,c67) are 16B-aligned for LDS.128 broadcast.
    __shared__ u64 Wp1[10][6];
    __shared__ u64 Wp2[10][6];
    // Per-warp slice: 1280 floats = p1 tile [0,640) | p2 tile [640,1280).
    // Reused (after syncwarp) as the 64x19=1216-float output tile.
    __shared__ float sbuf[WARPS * 1280];

    const int tid  = threadIdx.x;
    const int wid  = tid >> 5;
    const int lane = tid & 31;

    const size_t warpStart = (size_t)blockIdx.x * ROWS_PER_BLOCK
                           + (size_t)wid * ROWS_PER_WARP;
    const bool wfull = (warpStart + ROWS_PER_WARP) <= (size_t)B;
    float* slice = sbuf + wid * 1280;

    // --- stage 64 rows of p1/p2 FIRST so DRAM latency overlaps the barrier ---
    if (wfull) {
        const float4* s1 = (const float4*)(p1 + warpStart * 10);   // 160 float4
        const float4* s2 = (const float4*)(p2 + warpStart * 10);
        float4* d1 = (float4*)slice;
        float4* d2 = (float4*)(slice + 640);
        #pragma unroll
        for (int it = 0; it < 5; ++it) {
            const int i = lane + it * 32;
            d1[i] = __ldcs(&s1[i]);
            d2[i] = __ldcs(&s2[i]);
        }
    } else {
        const int rows = (warpStart < (size_t)B) ? (int)((size_t)B - warpStart) : 0;
        for (int i = lane; i < 1280; i += 32) slice[i] = 0.0f;
        __syncwarp();
        for (int i = lane; i < rows * 10; i += 32) {
            slice[i]       = p1[warpStart * 10 + i];
            slice[640 + i] = p2[warpStart * 10 + i];
        }
    }

    // --- weight normalization (20 threads; tiny uniform work) ---
    if (tid < 20) {
        const float* W = (tid < 10) ? W1 : W2;
        const int m = tid / 10;
        const int r = tid % 10;
        float row[10];
        #pragma unroll
        for (int c = 0; c < 10; ++c) row[c] = W[r * 10 + c];
        float lo = row[0], hi = row[0];
        #pragma unroll
        for (int c = 1; c < 10; ++c) { lo = fminf(lo, row[c]); hi = fmaxf(hi, row[c]); }
        const float ninv = -1.0f / (hi - lo + 1e-8f);      // negate here
        float* frow = m ? (float*)&Wp2[r][0] : (float*)&Wp1[r][0];
        #pragma unroll
        for (int c = 0; c < 10; ++c) frow[c] = (row[c] - lo) * ninv;
    }
    __syncthreads();   // the ONLY block-wide barrier (weights + own staging)

    const u64 ONE2 = pk2(1.0f);

    float A0[10], A1[10], B0v[10], B1v[10];

    // ---------- Phase A: A = clamp(1 - a @ Wn1), both elements ----------
    {
        float a0[10], a1[10];
        {
            const float2* v0 = (const float2*)(slice + lane * 10);
            const float2* v1 = (const float2*)(slice + (lane + 32) * 10);
            #pragma unroll
            for (int k = 0; k < 5; ++k) {
                float2 w = v0[k]; a0[2 * k] = w.x; a0[2 * k + 1] = w.y;
                float2 u = v1[k]; a1[2 * k] = u.x; a1[2 * k + 1] = u.y;
            }
        }
        u64 c0[5], c1[5];
        #pragma unroll
        for (int t = 0; t < 5; ++t) { c0[t] = ONE2; c1[t] = ONE2; }
        #pragma unroll
        for (int j = 0; j < 10; ++j) {
            const ulonglong2* wr = (const ulonglong2*)&Wp1[j][0];
            const ulonglong2 q0 = wr[0];
            const ulonglong2 q1 = wr[1];
            const u64        q2 = Wp1[j][4];
            const u64 x0 = pk2(a0[j]);
            const u64 x1 = pk2(a1[j]);
            fma2(c0[0], x0, q0.x); fma2(c0[1], x0, q0.y);
            fma2(c0[2], x0, q1.x); fma2(c0[3], x0, q1.y); fma2(c0[4], x0, q2);
            fma2(c1[0], x1, q0.x); fma2(c1[1], x1, q0.y);
            fma2(c1[2], x1, q1.x); fma2(c1[3], x1, q1.y); fma2(c1[4], x1, q2);
        }
        #pragma unroll
        for (int t = 0; t < 5; ++t) {
            float2 u = upk(c0[t]);
            A0[2 * t] = clampP(u.x); A0[2 * t + 1] = clampP(u.y);
            float2 v = upk(c1[t]);
            A1[2 * t] = clampP(v.x); A1[2 * t + 1] = clampP(v.y);
        }
    }

    // ---------- Phase B: B = clamp(1 - b @ Wn2), both elements ----------
    {
        float b0[10], b1[10];
        {
            const float2* v0 = (const float2*)(slice + 640 + lane * 10);
            const float2* v1 = (const float2*)(slice + 640 + (lane + 32) * 10);
            #pragma unroll
            for (int k = 0; k < 5; ++k) {
                float2 w = v0[k]; b0[2 * k] = w.x; b0[2 * k + 1] = w.y;
                float2 u = v1[k]; b1[2 * k] = u.x; b1[2 * k + 1] = u.y;
            }
        }
        u64 c0[5], c1[5];
        #pragma unroll
        for (int t = 0; t < 5; ++t) { c0[t] = ONE2; c1[t] = ONE2; }
        #pragma unroll
        for (int j = 0; j < 10; ++j) {
            const ulonglong2* wr = (const ulonglong2*)&Wp2[j][0];
            const ulonglong2 q0 = wr[0];
            const ulonglong2 q1 = wr[1];
            const u64        q2 = Wp2[j][4];
            const u64 x0 = pk2(b0[j]);
            const u64 x1 = pk2(b1[j]);
            fma2(c0[0], x0, q0.x); fma2(c0[1], x0, q0.y);
            fma2(c0[2], x0, q1.x); fma2(c0[3], x0, q1.y); fma2(c0[4], x0, q2);
            fma2(c1[0], x1, q0.x); fma2(c1[1], x1, q0.y);
            fma2(c1[2], x1, q1.x); fma2(c1[3], x1, q1.y); fma2(c1[4], x1, q2);
        }
        #pragma unroll
        for (int t = 0; t < 5; ++t) {
            float2 u = upk(c0[t]);
            B0v[2 * t] = clampP(u.x); B0v[2 * t + 1] = clampP(u.y);
            float2 v = upk(c1[t]);
            B1v[2 * t] = clampP(v.x); B1v[2 * t + 1] = clampP(v.y);
        }
    }
    __syncwarp();   // all slice reads done; slice becomes output tile

    // ---------- sequential epilogues, writing straight to shared ----------
    epilogue(A0, B0v, slice + lane * 19);
    epilogue(A1, B1v, slice + (lane + 32) * 19);
    __syncwarp();

    // ---------- coalesced store of the 64x19 output tile ----------
    if (wfull) {
        float4* dst = (float4*)(out + warpStart * 19);
        const float4* src = (const float4*)slice;
        #pragma unroll
        for (int it = 0; it < 10; ++it) {
            const int i = lane + it * 32;
            if (i < 304) __stcs(&dst[i], src[i]);     // 64*19/4 = 304
        }
    } else {
        const int rows = (warpStart < (size_t)B) ? (int)((size_t)B - warpStart) : 0;
        for (int i = lane; i < rows * 19; i += 32) out[warpStart * 19 + i] = slice[i];
    }
}

extern "C" void kernel_launch(void* const* d_in, const int* in_sizes, int n_in,
                              void* d_out, int out_size) {
    const float* p1 = (const float*)d_in[0];
    const float* p2 = (const float*)d_in[1];
    const float* W1 = (const float*)d_in[2];
    const float* W2 = (const float*)d_in[3];
    // d_in[4] = mask: structurally i+j==k, hardcoded.
    float* out = (float*)d_out;

    const int B = in_sizes[0] / 10;
    const int blocks = (B + ROWS_PER_BLOCK - 1) / ROWS_PER_BLOCK;
    bacon_kernel<<<blocks, THREADS>>>(p1, p2, W1, W2, out, B);
}

// round 12
// speedup vs baseline: 1.1158x; 1.0727x over previous
#include <cuda_runtime.h>

// BaconAdditionReasoner:
//   Wn = rowwise minmax-norm(W);  ap = a @ Wn1;  bp = b @ Wn2
//   A_i = clamp(1-ap_i, 1e-6, 1-1e-6); B_j likewise
//   prod[k] = prod_{i+j=k} max(A_i, B_j)   ( == exp(sum log(1-clip(min))) )
//   y[k] = (1 - prod[k]) / (19 - sum(prod) + 1e-9)
// mask input (d_in[4]) is structurally i+j==k -> hardcoded.
//
// 2 CONSECUTIVE rows per thread (2*lane, 2*lane+1): the 20 input floats are
// one contiguous 80B span -> 5 direct LDG.128 per input, NO input smem
// staging. Packed f32x2 matvecs share weight LDS across both rows; scalar
// epilogue writes straight to the per-warp smem output tile.

#define THREADS 128
#define WARPS (THREADS / 32)
#define ROWS_PER_WARP 64
#define ROWS_PER_BLOCK (THREADS * 2)
#define EPS_LO 1e-6f
#define EPS_HI (1.0f - 1e-6f)

typedef unsigned long long u64;

__device__ __forceinline__ u64 pk2(float x) {
    u64 r; asm("mov.b64 %0, {%1, %1};" : "=l"(r) : "f"(x)); return r;
}
__device__ __forceinline__ void fma2(u64& d, u64 a, u64 b) {
    asm("fma.rn.f32x2 %0, %1, %2, %0;" : "+l"(d) : "l"(a), "l"(b));
}
__device__ __forceinline__ float2 upk(u64 v) {
    float2 r; asm("mov.b64 {%0, %1}, %2;" : "=f"(r.x), "=f"(r.y) : "l"(v)); return r;
}
__device__ __forceinline__ float clampP(float x) {
    return fminf(fmaxf(x, EPS_LO), EPS_HI);
}

// Scalar epilogue; writes the 19 normalized outputs directly to smem (dst).
__device__ __forceinline__ void epilogue(const float* A, const float* Bv,
                                         float* __restrict__ dst) {
    float prod[19];
    #pragma unroll
    for (int k = 0; k < 10; ++k) prod[k] = fmaxf(A[0], Bv[k]);
    #pragma unroll
    for (int i = 1; i < 10; ++i) prod[9 + i] = fmaxf(A[i], Bv[9]);
    #pragma unroll
    for (int i = 1; i < 10; ++i) {
        const float Ai = A[i];
        #pragma unroll
        for (int j = 0; j < 9; ++j) prod[i + j] *= fmaxf(Ai, Bv[j]);
    }
    float sp = 0.0f;
    #pragma unroll
    for (int k = 0; k < 19; ++k) sp += prod[k];
    const float inv = __fdividef(1.0f, (19.0f - sp) + 1e-9f);
    #pragma unroll
    for (int k = 0; k < 19; ++k) dst[k] = fmaf(-prod[k], inv, inv);
}

// Packed matvec for a row pair: c[t] = 1 - (rows @ Wn), rows from in[20].
// in[0..9] = row0, in[10..19] = row1; Wp rows are 5 u64 (negated weights).
__device__ __forceinline__ void matvec_pair(const float* in, const u64 (*Wp)[6],
                                            u64 ONE2, u64* c0, u64* c1) {
    #pragma unroll
    for (int t = 0; t < 5; ++t) { c0[t] = ONE2; c1[t] = ONE2; }
    #pragma unroll
    for (int j = 0; j < 10; ++j) {
        const ulonglong2* wr = (const ulonglong2*)&Wp[j][0];
        const ulonglong2 q0 = wr[0];          // pairs c01, c23
        const ulonglong2 q1 = wr[1];          // pairs c45, c67
        const u64        q2 = Wp[j][4];       // pair  c89
        const u64 x0 = pk2(in[j]);
        const u64 x1 = pk2(in[10 + j]);
        fma2(c0[0], x0, q0.x); fma2(c0[1], x0, q0.y);
        fma2(c0[2], x0, q1.x); fma2(c0[3], x0, q1.y); fma2(c0[4], x0, q2);
        fma2(c1[0], x1, q0.x); fma2(c1[1], x1, q0.y);
        fma2(c1[2], x1, q1.x); fma2(c1[3], x1, q1.y); fma2(c1[4], x1, q2);
    }
}

__global__ void __launch_bounds__(THREADS, 7) bacon_kernel(
    const float* __restrict__ p1, const float* __restrict__ p2,
    const float* __restrict__ W1, const float* __restrict__ W2,
    float* __restrict__ out, int B)
{
    // NEGATED normalized weights; row = 5 u64 pairs, padded to 6 (48B) so
    // pairs (c01,c23) and (c45,c67) are 16B-aligned for LDS.128 broadcast.
    __shared__ u64 Wp1[10][6];
    __shared__ u64 Wp2[10][6];
    // Per-warp 64x19 output tile (1216 floats).
    __shared__ float sbuf[WARPS * 1216];

    const int tid  = threadIdx.x;
    const int wid  = tid >> 5;
    const int lane = tid & 31;

    const size_t warpStart = (size_t)blockIdx.x * ROWS_PER_BLOCK
                           + (size_t)wid * ROWS_PER_WARP;
    const bool wfull = (warpStart + ROWS_PER_WARP) <= (size_t)B;
    float* slice = sbuf + wid * 1216;

    // --- direct input loads: rows 2*lane, 2*lane+1 = 80B contiguous ---
    float av[20], bv[20];     // [0..9] row0, [10..19] row1
    if (wfull) {
        const float4* s1 = (const float4*)(p1 + warpStart * 10) + lane * 5;
        const float4* s2 = (const float4*)(p2 + warpStart * 10) + lane * 5;
        #pragma unroll
        for (int i = 0; i < 5; ++i) {
            const float4 x = __ldcs(&s1[i]);
            av[4 * i + 0] = x.x; av[4 * i + 1] = x.y;
            av[4 * i + 2] = x.z; av[4 * i + 3] = x.w;
            const float4 y = __ldcs(&s2[i]);
            bv[4 * i + 0] = y.x; bv[4 * i + 1] = y.y;
            bv[4 * i + 2] = y.z; bv[4 * i + 3] = y.w;
        }
    } else {
        const size_t r0 = warpStart + 2 * (size_t)lane;
        #pragma unroll
        for (int e = 0; e < 2; ++e) {
            const size_t r = r0 + e;
            if (r < (size_t)B) {
                #pragma unroll
                for (int j = 0; j < 10; ++j) {
                    av[10 * e + j] = p1[r * 10 + j];
                    bv[10 * e + j] = p2[r * 10 + j];
                }
            } else {
                #pragma unroll
                for (int j = 0; j < 10; ++j) { av[10 * e + j] = 0.5f; bv[10 * e + j] = 0.5f; }
            }
        }
    }

    // --- weight normalization (20 threads; tiny uniform work) ---
    if (tid < 20) {
        const float* W = (tid < 10) ? W1 : W2;
        const int m = tid / 10;
        const int r = tid % 10;
        float row[10];
        #pragma unroll
        for (int c = 0; c < 10; ++c) row[c] = W[r * 10 + c];
        float lo = row[0], hi = row[0];
        #pragma unroll
        for (int c = 1; c < 10; ++c) { lo = fminf(lo, row[c]); hi = fmaxf(hi, row[c]); }
        const float ninv = -1.0f / (hi - lo + 1e-8f);      // negate here
        float* frow = m ? (float*)&Wp2[r][0] : (float*)&Wp1[r][0];
        #pragma unroll
        for (int c = 0; c < 10; ++c) frow[c] = (row[c] - lo) * ninv;
    }
    __syncthreads();   // the ONLY block-wide barrier (weights ready)

    const u64 ONE2 = pk2(1.0f);

    float A0[10], A1[10], B0v[10], B1v[10];

    // ---------- Phase A: A = clamp(1 - a @ Wn1), both rows ----------
    {
        u64 c0[5], c1[5];
        matvec_pair(av, Wp1, ONE2, c0, c1);
        #pragma unroll
        for (int t = 0; t < 5; ++t) {
            float2 u = upk(c0[t]);
            A0[2 * t] = clampP(u.x); A0[2 * t + 1] = clampP(u.y);
            float2 v = upk(c1[t]);
            A1[2 * t] = clampP(v.x); A1[2 * t + 1] = clampP(v.y);
        }
    }

    // ---------- Phase B: B = clamp(1 - b @ Wn2), both rows ----------
    {
        u64 c0[5], c1[5];
        matvec_pair(bv, Wp2, ONE2, c0, c1);
        #pragma unroll
        for (int t = 0; t < 5; ++t) {
            float2 u = upk(c0[t]);
            B0v[2 * t] = clampP(u.x); B0v[2 * t + 1] = clampP(u.y);
            float2 v = upk(c1[t]);
            B1v[2 * t] = clampP(v.x); B1v[2 * t + 1] = clampP(v.y);
        }
    }

    // ---------- epilogues straight into the smem tile (rows 2lane, 2lane+1) --
    epilogue(A0, B0v, slice + (2 * lane) * 19);
    epilogue(A1, B1v, slice + (2 * lane + 1) * 19);
    __syncwarp();

    // ---------- coalesced store of the 64x19 output tile ----------
    if (wfull) {
        float4* dst = (float4*)(out + warpStart * 19);
        const float4* src = (const float4*)slice;
        #pragma unroll
        for (int it = 0; it < 10; ++it) {
            const int i = lane + it * 32;
            if (i < 304) __stcs(&dst[i], src[i]);     // 64*19/4 = 304
        }
    } else {
        const int rows = (warpStart < (size_t)B) ? (int)((size_t)B - warpStart) : 0;
        for (int i = lane; i < rows * 19; i += 32) out[warpStart * 19 + i] = slice[i];
    }
}

extern "C" void kernel_launch(void* const* d_in, const int* in_sizes, int n_in,
                              void* d_out, int out_size) {
    const float* p1 = (const float*)d_in[0];
    const float* p2 = (const float*)d_in[1];
    const float* W1 = (const float*)d_in[2];
    const float* W2 = (const float*)d_in[3];
    // d_in[4] = mask: structurally i+j==k, hardcoded.
    float* out = (float*)d_out;

    const int B = in_sizes[0] / 10;
    const int blocks = (B + ROWS_PER_BLOCK - 1) / ROWS_PER_BLOCK;
    bacon_kernel<<<blocks, THREADS>>>(p1, p2, W1, W2, out, B);
}